// round 13
// baseline (speedup 1.0000x reference)
#include <cuda_runtime.h>
#include <cuda_bf16.h>
#include <cstdint>

#define BN    2048
#define DD    32
#define NIDS  8192
#define KNN   30
#define NTHR  256
#define MT    64                // rows per den CTA
#define NT    128               // cols per den CTA
#define XT    (BN / MT)         // 32
#define YT    (BN / NT)         // 16
#define NCTAS_ALL (XT * (YT + 1))    // 544
#define BCAP  32
#define RS    144               // smem row stride: 128B (hi|lo) + 16B pad

// Scratch (no allocations allowed)
__device__ float g_sq[BN];
__device__ __align__(16) unsigned g_zhl[BN * 32];  // 128B/row: 16 u32 hi | 16 u32 lo
__device__ float g_pden[YT * BN];
__device__ float g_num[BN];
__device__ float g_any[BN];
__device__ int   g_bkt[NIDS * BCAP];
__device__ int   g_bcnt[NIDS];
__device__ unsigned g_cnt = 0;

__device__ __forceinline__ float fsqrt_approx(float x) {
    float r; asm("sqrt.approx.f32 %0, %1;" : "=f"(r) : "f"(x)); return r;
}
__device__ __forceinline__ float pair_e(float dot, float sqsum) {
    float d2 = fmaf(-2.f, dot, sqsum);
    d2 = fmaxf(d2, 1e-20f);
    return __expf(-fsqrt_approx(d2));
}
__device__ __forceinline__ uint32_t bpack(__nv_bfloat16 a, __nv_bfloat16 b) {
    __nv_bfloat162 p; p.x = a; p.y = b;
    return *reinterpret_cast<uint32_t*>(&p);
}
__device__ __forceinline__ void mma_bf16(float* d, const uint32_t* a,
                                         const uint32_t* b, const float* c) {
    asm volatile(
        "mma.sync.aligned.m16n8k16.row.col.f32.bf16.bf16.f32 "
        "{%0,%1,%2,%3}, {%4,%5,%6,%7}, {%8,%9}, {%10,%11,%12,%13};"
        : "=f"(d[0]), "=f"(d[1]), "=f"(d[2]), "=f"(d[3])
        : "r"(a[0]), "r"(a[1]), "r"(a[2]), "r"(a[3]),
          "r"(b[0]), "r"(b[1]),
          "f"(c[0]), "f"(c[1]), "f"(c[2]), "f"(c[3]));
}

// Kernel 1: grid 65. bid<64: hi/lo split + norms. bid==64: bucket fill.
__global__ void __launch_bounds__(NTHR)
prep_kernel(const float* __restrict__ z, const int* __restrict__ sid) {
    const int t = threadIdx.x;
    if (blockIdx.x < 64) {
        const int gid = blockIdx.x * NTHR + t;
        const int r = gid >> 3, c = gid & 7;
        float4 v = ((const float4*)z)[r * 8 + c];
        float s = v.x * v.x + v.y * v.y + v.z * v.z + v.w * v.w;
        s += __shfl_xor_sync(0xffffffffu, s, 1);
        s += __shfl_xor_sync(0xffffffffu, s, 2);
        s += __shfl_xor_sync(0xffffffffu, s, 4);
        if (c == 0) g_sq[r] = s;

        __nv_bfloat16 hx = __float2bfloat16(v.x), hy = __float2bfloat16(v.y);
        __nv_bfloat16 hz = __float2bfloat16(v.z), hw = __float2bfloat16(v.w);
        __nv_bfloat16 lx = __float2bfloat16(v.x - __bfloat162float(hx));
        __nv_bfloat16 ly = __float2bfloat16(v.y - __bfloat162float(hy));
        __nv_bfloat16 lz = __float2bfloat16(v.z - __bfloat162float(hz));
        __nv_bfloat16 lw = __float2bfloat16(v.w - __bfloat162float(hw));
        g_zhl[r * 32 + c * 2]          = bpack(hx, hy);
        g_zhl[r * 32 + c * 2 + 1]      = bpack(hz, hw);
        g_zhl[r * 32 + 16 + c * 2]     = bpack(lx, ly);
        g_zhl[r * 32 + 16 + c * 2 + 1] = bpack(lz, lw);
    } else {
        for (int j = t; j < BN; j += NTHR) {
            int id = sid[j];
            int slot = atomicAdd(&g_bcnt[id], 1);
            if (slot < BCAP) g_bkt[id * BCAP + slot] = j;
        }
    }
}

// Kernel 2: grid (32, 17).
//  y<16 : den tile 64x128 via mma.sync bf16 hi/lo; diag skipped by index.
//  y==16: sparse num/valid (warp per row group, 8 rows each).
// Last of 544 CTAs: final scalar reduction + scratch reset.
__global__ void __launch_bounds__(NTHR, 3)
main_kernel(const float* __restrict__ z,
            const int* __restrict__ knn,
            const int* __restrict__ sid,
            float* __restrict__ out) {
    __shared__ __align__(16) char s_a[MT * RS];
    __shared__ __align__(16) char s_b[NT * RS];
    __shared__ float s_pd[MT][4];
    __shared__ float s_sqi[MT];
    __shared__ float s_sqj[NT];
    __shared__ bool s_last;

    const int t = threadIdx.x;
    const int w = t >> 5, lane = t & 31;
    const int gID = lane >> 2, tig = lane & 3;
    const int x = blockIdx.x, y = blockIdx.y;

    if (y < YT) {
        // ---- load tiles: A = rows [x*64,+64), B = rows [y*128,+128) ----
        const uint4* src = (const uint4*)g_zhl;
#pragma unroll
        for (int i = t; i < NT * 8; i += NTHR) {
            int row = i >> 3, u = i & 7;
            if (i < MT * 8)
                *(uint4*)(s_a + row * RS + u * 16) = src[(x * MT + row) * 8 + u];
            *(uint4*)(s_b + row * RS + u * 16) = src[(y * NT + row) * 8 + u];
        }
        if (t < MT) s_sqi[t] = g_sq[x * MT + t];
        else if (t < MT + NT) s_sqj[t - MT] = g_sq[y * NT + (t - MT)];
        __syncthreads();

        // ---- warp tile 32x32: wm in 0..1 (rows), wn in 0..3 (cols) ----
        const int wm = w & 1, wn = w >> 1;
        float acc[2][4][4];
#pragma unroll
        for (int mi = 0; mi < 2; mi++)
#pragma unroll
            for (int ni = 0; ni < 4; ni++)
#pragma unroll
                for (int q = 0; q < 4; q++) acc[mi][ni][q] = 0.f;

        // combos: 0 = hi*hi, 1 = hi*lo, 2 = lo*hi  (lo at +64B)
#pragma unroll
        for (int combo = 0; combo < 3; combo++) {
            const int aoff = (combo == 2) ? 64 : 0;
            const int boff = (combo == 1) ? 64 : 0;
#pragma unroll
            for (int kk = 0; kk < 2; kk++) {
                const int ka = aoff + kk * 32 + tig * 4;
                const int kb = boff + kk * 32 + tig * 4;
                uint32_t af[2][4];
#pragma unroll
                for (int mi = 0; mi < 2; mi++) {
                    const char* base = s_a + (wm * 32 + mi * 16 + gID) * RS;
                    af[mi][0] = *(const uint32_t*)(base + ka);
                    af[mi][1] = *(const uint32_t*)(base + 8 * RS + ka);
                    af[mi][2] = *(const uint32_t*)(base + ka + 16);
                    af[mi][3] = *(const uint32_t*)(base + 8 * RS + ka + 16);
                }
#pragma unroll
                for (int ni = 0; ni < 4; ni++) {
                    const char* bb = s_b + (wn * 32 + ni * 8 + gID) * RS;
                    uint32_t bf[2];
                    bf[0] = *(const uint32_t*)(bb + kb);
                    bf[1] = *(const uint32_t*)(bb + kb + 16);
                    mma_bf16(acc[0][ni], af[0], bf, acc[0][ni]);
                    mma_bf16(acc[1][ni], af[1], bf, acc[1][ni]);
                }
            }
        }

        // ---- epilogue: exp(-sqrt(d2)), skip diagonal, row sums ----
#pragma unroll
        for (int mi = 0; mi < 2; mi++) {
            const int lr0 = wm * 32 + mi * 16 + gID;
            const int lr1 = lr0 + 8;
            const int gi0 = x * MT + lr0, gi1 = x * MT + lr1;
            const float sq0 = s_sqi[lr0], sq1 = s_sqi[lr1];
            float rs0 = 0.f, rs1 = 0.f;
#pragma unroll
            for (int ni = 0; ni < 4; ni++) {
                const int cl = wn * 32 + ni * 8 + tig * 2;
                const int gj0 = y * NT + cl, gj1 = gj0 + 1;
                const float sa = s_sqj[cl], sb = s_sqj[cl + 1];
                float e;
                e = pair_e(acc[mi][ni][0], sq0 + sa); rs0 += (gj0 == gi0) ? 0.f : e;
                e = pair_e(acc[mi][ni][1], sq0 + sb); rs0 += (gj1 == gi0) ? 0.f : e;
                e = pair_e(acc[mi][ni][2], sq1 + sa); rs1 += (gj0 == gi1) ? 0.f : e;
                e = pair_e(acc[mi][ni][3], sq1 + sb); rs1 += (gj1 == gi1) ? 0.f : e;
            }
            rs0 += __shfl_xor_sync(0xffffffffu, rs0, 1);
            rs0 += __shfl_xor_sync(0xffffffffu, rs0, 2);
            rs1 += __shfl_xor_sync(0xffffffffu, rs1, 1);
            rs1 += __shfl_xor_sync(0xffffffffu, rs1, 2);
            if (tig == 0) { s_pd[lr0][wn] = rs0; s_pd[lr1][wn] = rs1; }
        }
        __syncthreads();
        if (t < MT)
            g_pden[y * BN + x * MT + t] =
                (s_pd[t][0] + s_pd[t][1]) + (s_pd[t][2] + s_pd[t][3]);
    } else {
        // ---- sparse num / valid: 8 warps x 8 rows = rows [x*64,+64) ----
#pragma unroll 1
        for (int rr = 0; rr < 8; rr++) {
            const int i = x * MT + w * 8 + rr;
            const int sidi = sid[i];
            int id = (lane < KNN) ? knn[sidi * KNN + lane] : -1;
            bool dup = false;
#pragma unroll
            for (int p = 0; p < KNN; p++) {
                int idp = __shfl_sync(0xffffffffu, id, p);
                dup = dup || (p < lane && idp == id);
            }
            float num = 0.f;
            bool found = false;
            if (lane < KNN && !dup) {
                int cnt = g_bcnt[id];
                if (cnt > BCAP) cnt = BCAP;
                if (cnt > 0) {
                    int jarr[BCAP];
                    for (int s2 = 0; s2 < cnt; s2++) jarr[s2] = g_bkt[id * BCAP + s2];
                    for (int a = 1; a < cnt; a++) {   // sort -> deterministic order
                        int v = jarr[a]; int b = a - 1;
                        while (b >= 0 && jarr[b] > v) { jarr[b + 1] = jarr[b]; b--; }
                        jarr[b + 1] = v;
                    }
                    for (int s2 = 0; s2 < cnt; s2++) {
                        int jj = jarr[s2];
                        if (jj != i) {
                            const float* zi = z + i * DD;
                            const float* zj = z + jj * DD;
                            float dot = 0.f;
#pragma unroll
                            for (int k = 0; k < DD; k++) dot = fmaf(zi[k], zj[k], dot);
                            num += pair_e(dot, g_sq[i] + g_sq[jj]);
                            found = true;
                        }
                    }
                }
            }
#pragma unroll
            for (int off = 16; off > 0; off >>= 1)
                num += __shfl_xor_sync(0xffffffffu, num, off);
            unsigned bal = __ballot_sync(0xffffffffu, found);
            if (lane == 0) {
                g_num[i] = num;
                g_any[i] = bal ? 1.f : 0.f;
            }
        }
    }

    // ---- last-block final reduction (deterministic) ----
    __threadfence();
    if (t == 0) {
        unsigned old = atomicAdd(&g_cnt, 1u);
        s_last = (old == NCTAS_ALL - 1);
    }
    __syncthreads();
    if (!s_last) return;

    __threadfence();
    float tot = 0.f, cnt = 0.f;
    for (int i = t; i < BN; i += NTHR) {
        float dv = 0.f;
#pragma unroll
        for (int yy = 0; yy < YT; yy++) dv += __ldcg(&g_pden[yy * BN + i]);
        float nv = __ldcg(&g_num[i]);
        bool valid = __ldcg(&g_any[i]) > 0.f;
        float sr = nv / dv;
        float loss = -__logf(sr + 1e-8f);
        tot += valid ? loss : 0.f;
        cnt += valid ? 1.f : 0.f;
    }
#pragma unroll
    for (int off = 16; off > 0; off >>= 1) {
        tot += __shfl_xor_sync(0xffffffffu, tot, off);
        cnt += __shfl_xor_sync(0xffffffffu, cnt, off);
    }
    if (lane == 0) { s_pd[w][0] = tot; s_pd[w][1] = cnt; }
    __syncthreads();
    if (t == 0) {
        float T = 0.f, C = 0.f;
#pragma unroll
        for (int ww = 0; ww < NTHR / 32; ww++) { T += s_pd[ww][0]; C += s_pd[ww][1]; }
        out[0] = (C > 0.f) ? (T / C) : 0.f;
        g_cnt = 0;
    }
    for (int i = t; i < NIDS; i += NTHR) g_bcnt[i] = 0;  // reset for next replay
}

extern "C" void kernel_launch(void* const* d_in, const int* in_sizes, int n_in,
                              void* d_out, int out_size) {
    const float* z   = (const float*)d_in[0];
    const int*   knn = (const int*)d_in[1];
    const int*   sid = (const int*)d_in[2];
    (void)in_sizes; (void)n_in; (void)out_size;

    prep_kernel<<<65, NTHR>>>(z, sid);
    main_kernel<<<dim3(XT, YT + 1, 1), NTHR>>>(z, knn, sid, (float*)d_out);
}

// round 14
// speedup vs baseline: 1.6552x; 1.6552x over previous
#include <cuda_runtime.h>
#include <cuda_bf16.h>
#include <cstdint>

#define BN    2048
#define DD    32
#define NIDS  8192
#define KNN   30
#define NTHR  256
#define MT    128               // rows per den CTA
#define NT    64                // cols per den CTA
#define XT    (BN / MT)         // 16
#define YT    (BN / NT)         // 32
#define SPY   8                 // sparse y-slots (warp per 2 rows)
#define NCTAS_ALL (XT * (YT + SPY))  // 640
#define BCAP  32
#define RS    144               // smem row stride: 128B (hi|lo) + 16B pad

// Scratch (no allocations allowed)
__device__ float g_sq[BN];
__device__ __align__(16) unsigned g_zhl[BN * 32];  // 128B/row: 16 u32 hi | 16 u32 lo
__device__ float g_pden[YT * BN];
__device__ float g_num[BN];
__device__ float g_any[BN];
__device__ int   g_bkt[NIDS * BCAP];
__device__ int   g_bcnt[NIDS];
__device__ unsigned g_cnt = 0;

__device__ __forceinline__ float fsqrt_approx(float x) {
    float r; asm("sqrt.approx.f32 %0, %1;" : "=f"(r) : "f"(x)); return r;
}
__device__ __forceinline__ float pair_e(float dot, float sqsum) {
    float d2 = fmaf(-2.f, dot, sqsum);
    d2 = fmaxf(d2, 1e-20f);
    return __expf(-fsqrt_approx(d2));
}
__device__ __forceinline__ uint32_t bpack(__nv_bfloat16 a, __nv_bfloat16 b) {
    __nv_bfloat162 p; p.x = a; p.y = b;
    return *reinterpret_cast<uint32_t*>(&p);
}
__device__ __forceinline__ void mma_bf16(float* d, const uint32_t* a,
                                         const uint32_t* b, const float* c) {
    asm volatile(
        "mma.sync.aligned.m16n8k16.row.col.f32.bf16.bf16.f32 "
        "{%0,%1,%2,%3}, {%4,%5,%6,%7}, {%8,%9}, {%10,%11,%12,%13};"
        : "=f"(d[0]), "=f"(d[1]), "=f"(d[2]), "=f"(d[3])
        : "r"(a[0]), "r"(a[1]), "r"(a[2]), "r"(a[3]),
          "r"(b[0]), "r"(b[1]),
          "f"(c[0]), "f"(c[1]), "f"(c[2]), "f"(c[3]));
}

// Kernel 1: grid 72. bid<64: hi/lo split + norms. bid>=64: bucket fill.
__global__ void __launch_bounds__(NTHR)
prep_kernel(const float* __restrict__ z, const int* __restrict__ sid) {
    const int t = threadIdx.x;
    if (blockIdx.x < 64) {
        const int gid = blockIdx.x * NTHR + t;
        const int r = gid >> 3, c = gid & 7;
        float4 v = ((const float4*)z)[r * 8 + c];
        float s = v.x * v.x + v.y * v.y + v.z * v.z + v.w * v.w;
        s += __shfl_xor_sync(0xffffffffu, s, 1);
        s += __shfl_xor_sync(0xffffffffu, s, 2);
        s += __shfl_xor_sync(0xffffffffu, s, 4);
        if (c == 0) g_sq[r] = s;

        __nv_bfloat16 hx = __float2bfloat16(v.x), hy = __float2bfloat16(v.y);
        __nv_bfloat16 hz = __float2bfloat16(v.z), hw = __float2bfloat16(v.w);
        __nv_bfloat16 lx = __float2bfloat16(v.x - __bfloat162float(hx));
        __nv_bfloat16 ly = __float2bfloat16(v.y - __bfloat162float(hy));
        __nv_bfloat16 lz = __float2bfloat16(v.z - __bfloat162float(hz));
        __nv_bfloat16 lw = __float2bfloat16(v.w - __bfloat162float(hw));
        g_zhl[r * 32 + c * 2]          = bpack(hx, hy);
        g_zhl[r * 32 + c * 2 + 1]      = bpack(hz, hw);
        g_zhl[r * 32 + 16 + c * 2]     = bpack(lx, ly);
        g_zhl[r * 32 + 16 + c * 2 + 1] = bpack(lz, lw);
    } else {
        const int j = (blockIdx.x - 64) * NTHR + t;   // 8 CTAs cover 2048 j's
        const int id = sid[j];
        int slot = atomicAdd(&g_bcnt[id], 1);
        if (slot < BCAP) g_bkt[id * BCAP + slot] = j;
    }
}

// Kernel 2: grid (16, 40).
//  y<32 : den tile 128x64 via mma.sync bf16 hi/lo (warp tile 32x32); diag skipped by index.
//  y>=32: sparse num/valid (warp per 2 rows, 128 CTAs).
// Last of 640 CTAs: final scalar reduction + scratch reset.
__global__ void __launch_bounds__(NTHR, 3)
main_kernel(const float* __restrict__ z,
            const int* __restrict__ knn,
            const int* __restrict__ sid,
            float* __restrict__ out) {
    __shared__ __align__(16) char s_a[MT * RS];
    __shared__ __align__(16) char s_b[NT * RS];
    __shared__ float s_pd[MT][2];
    __shared__ float s_sqi[MT];
    __shared__ float s_sqj[NT];
    __shared__ bool s_last;

    const int t = threadIdx.x;
    const int w = t >> 5, lane = t & 31;
    const int gID = lane >> 2, tig = lane & 3;
    const int x = blockIdx.x, y = blockIdx.y;

    if (y < YT) {
        // ---- load tiles: A = rows [x*128,+128), B = rows [y*64,+64) ----
        const uint4* src = (const uint4*)g_zhl;
#pragma unroll
        for (int i = t; i < (MT + NT) * 8; i += NTHR) {
            int row = i >> 3, u = i & 7;
            if (i < MT * 8)
                *(uint4*)(s_a + row * RS + u * 16) = src[(x * MT + row) * 8 + u];
            else {
                int r2 = row - MT;
                *(uint4*)(s_b + r2 * RS + u * 16) = src[(y * NT + r2) * 8 + u];
            }
        }
        if (t < MT) s_sqi[t] = g_sq[x * MT + t];
        else if (t < MT + NT) s_sqj[t - MT] = g_sq[y * NT + (t - MT)];
        __syncthreads();

        // ---- warp tile 32x32: wm in 0..3 (rows), wn in 0..1 (cols) ----
        const int wm = w & 3, wn = w >> 2;
        float acc[2][4][4];
#pragma unroll
        for (int mi = 0; mi < 2; mi++)
#pragma unroll
            for (int ni = 0; ni < 4; ni++)
#pragma unroll
                for (int q = 0; q < 4; q++) acc[mi][ni][q] = 0.f;

        // combos: 0 = hi*hi, 1 = hi*lo, 2 = lo*hi  (lo at +64B)
#pragma unroll
        for (int combo = 0; combo < 3; combo++) {
            const int aoff = (combo == 2) ? 64 : 0;
            const int boff = (combo == 1) ? 64 : 0;
#pragma unroll
            for (int kk = 0; kk < 2; kk++) {
                const int ka = aoff + kk * 32 + tig * 4;
                const int kb = boff + kk * 32 + tig * 4;
                uint32_t af[2][4];
#pragma unroll
                for (int mi = 0; mi < 2; mi++) {
                    const char* base = s_a + (wm * 32 + mi * 16 + gID) * RS;
                    af[mi][0] = *(const uint32_t*)(base + ka);
                    af[mi][1] = *(const uint32_t*)(base + 8 * RS + ka);
                    af[mi][2] = *(const uint32_t*)(base + ka + 16);
                    af[mi][3] = *(const uint32_t*)(base + 8 * RS + ka + 16);
                }
#pragma unroll
                for (int ni = 0; ni < 4; ni++) {
                    const char* bb = s_b + (wn * 32 + ni * 8 + gID) * RS;
                    uint32_t bf[2];
                    bf[0] = *(const uint32_t*)(bb + kb);
                    bf[1] = *(const uint32_t*)(bb + kb + 16);
                    mma_bf16(acc[0][ni], af[0], bf, acc[0][ni]);
                    mma_bf16(acc[1][ni], af[1], bf, acc[1][ni]);
                }
            }
        }

        // ---- epilogue: exp(-sqrt(d2)), skip diagonal, row sums ----
#pragma unroll
        for (int mi = 0; mi < 2; mi++) {
            const int lr0 = wm * 32 + mi * 16 + gID;
            const int lr1 = lr0 + 8;
            const int gi0 = x * MT + lr0, gi1 = x * MT + lr1;
            const float sq0 = s_sqi[lr0], sq1 = s_sqi[lr1];
            float rs0 = 0.f, rs1 = 0.f;
#pragma unroll
            for (int ni = 0; ni < 4; ni++) {
                const int cl = wn * 32 + ni * 8 + tig * 2;
                const int gj0 = y * NT + cl, gj1 = gj0 + 1;
                const float sa = s_sqj[cl], sb = s_sqj[cl + 1];
                float e;
                e = pair_e(acc[mi][ni][0], sq0 + sa); rs0 += (gj0 == gi0) ? 0.f : e;
                e = pair_e(acc[mi][ni][1], sq0 + sb); rs0 += (gj1 == gi0) ? 0.f : e;
                e = pair_e(acc[mi][ni][2], sq1 + sa); rs1 += (gj0 == gi1) ? 0.f : e;
                e = pair_e(acc[mi][ni][3], sq1 + sb); rs1 += (gj1 == gi1) ? 0.f : e;
            }
            rs0 += __shfl_xor_sync(0xffffffffu, rs0, 1);
            rs0 += __shfl_xor_sync(0xffffffffu, rs0, 2);
            rs1 += __shfl_xor_sync(0xffffffffu, rs1, 1);
            rs1 += __shfl_xor_sync(0xffffffffu, rs1, 2);
            if (tig == 0) { s_pd[lr0][wn] = rs0; s_pd[lr1][wn] = rs1; }
        }
        __syncthreads();
        if (t < MT)
            g_pden[y * BN + x * MT + t] = s_pd[t][0] + s_pd[t][1];
    } else {
        // ---- sparse num / valid: warp handles 2 rows (128 sparse CTAs) ----
        const int ysp = y - YT;
#pragma unroll
        for (int rr = 0; rr < 2; rr++) {
            const int i = x * MT + ysp * 16 + w * 2 + rr;
            const int sidi = sid[i];
            int id = (lane < KNN) ? knn[sidi * KNN + lane] : (-1 - lane);
            // one-instruction dedup: leader = lowest lane with this id
            unsigned mm = __match_any_sync(0xffffffffu, id);
            bool dup = (mm & ((1u << lane) - 1u)) != 0u;
            float num = 0.f;
            bool found = false;
            if (lane < KNN && !dup) {
                int cnt = g_bcnt[id];
                if (cnt > BCAP) cnt = BCAP;
                if (cnt > 0) {
                    int jarr[BCAP];
                    for (int s2 = 0; s2 < cnt; s2++) jarr[s2] = g_bkt[id * BCAP + s2];
                    for (int a = 1; a < cnt; a++) {   // sort -> deterministic order
                        int v = jarr[a]; int b = a - 1;
                        while (b >= 0 && jarr[b] > v) { jarr[b + 1] = jarr[b]; b--; }
                        jarr[b + 1] = v;
                    }
                    for (int s2 = 0; s2 < cnt; s2++) {
                        int jj = jarr[s2];
                        if (jj != i) {
                            const float* zi = z + i * DD;
                            const float* zj = z + jj * DD;
                            float dot = 0.f;
#pragma unroll
                            for (int k = 0; k < DD; k++) dot = fmaf(zi[k], zj[k], dot);
                            num += pair_e(dot, g_sq[i] + g_sq[jj]);
                            found = true;
                        }
                    }
                }
            }
#pragma unroll
            for (int off = 16; off > 0; off >>= 1)
                num += __shfl_xor_sync(0xffffffffu, num, off);
            unsigned bal = __ballot_sync(0xffffffffu, found);
            if (lane == 0) {
                g_num[i] = num;
                g_any[i] = bal ? 1.f : 0.f;
            }
        }
    }

    // ---- last-block final reduction (deterministic) ----
    __threadfence();
    if (t == 0) {
        unsigned old = atomicAdd(&g_cnt, 1u);
        s_last = (old == NCTAS_ALL - 1);
    }
    __syncthreads();
    if (!s_last) return;

    __threadfence();
    float tot = 0.f, cnt = 0.f;
    for (int i = t; i < BN; i += NTHR) {
        float dv = 0.f;
#pragma unroll
        for (int yy = 0; yy < YT; yy++) dv += __ldcg(&g_pden[yy * BN + i]);
        float nv = __ldcg(&g_num[i]);
        bool valid = __ldcg(&g_any[i]) > 0.f;
        float sr = nv / dv;
        float loss = -__logf(sr + 1e-8f);
        tot += valid ? loss : 0.f;
        cnt += valid ? 1.f : 0.f;
    }
#pragma unroll
    for (int off = 16; off > 0; off >>= 1) {
        tot += __shfl_xor_sync(0xffffffffu, tot, off);
        cnt += __shfl_xor_sync(0xffffffffu, cnt, off);
    }
    if (lane == 0) { s_pd[w][0] = tot; s_pd[w][1] = cnt; }
    __syncthreads();
    if (t == 0) {
        float T = 0.f, C = 0.f;
#pragma unroll
        for (int ww = 0; ww < NTHR / 32; ww++) { T += s_pd[ww][0]; C += s_pd[ww][1]; }
        out[0] = (C > 0.f) ? (T / C) : 0.f;
        g_cnt = 0;
    }
    for (int i = t; i < NIDS; i += NTHR) g_bcnt[i] = 0;  // reset for next replay
}

extern "C" void kernel_launch(void* const* d_in, const int* in_sizes, int n_in,
                              void* d_out, int out_size) {
    const float* z   = (const float*)d_in[0];
    const int*   knn = (const int*)d_in[1];
    const int*   sid = (const int*)d_in[2];
    (void)in_sizes; (void)n_in; (void)out_size;

    prep_kernel<<<72, NTHR>>>(z, sid);
    main_kernel<<<dim3(XT, YT + SPY, 1), NTHR>>>(z, knn, sid, (float*)d_out);
}

// round 15
// speedup vs baseline: 1.7778x; 1.0741x over previous
#include <cuda_runtime.h>
#include <cuda_bf16.h>
#include <cstdint>

#define BN    2048
#define DD    32
#define NIDS  8192
#define KNN   30
#define NTHR  256
#define MT    128               // rows per den CTA
#define NT    64                // cols per den CTA
#define XT    (BN / MT)         // 16
#define YT    (BN / NT)         // 32
#define SPY   8                 // sparse y-slots (warp per 2 rows)
#define NCTAS_ALL (XT * (YT + SPY))  // 640
#define BCAP  32
#define RS    144               // smem row stride: 128B (hi|lo) + 16B pad

// Scratch (no allocations allowed)
__device__ float g_sq[BN];
__device__ __align__(16) unsigned g_zhl[BN * 32];  // 128B/row: 16 u32 hi | 16 u32 lo
__device__ float g_den[BN];      // atomic fp32 accumulation (zeroed by prep)
__device__ float g_num[BN];
__device__ float g_any[BN];
__device__ int   g_bkt[NIDS * BCAP];
__device__ int   g_bcnt[NIDS];
__device__ unsigned g_cnt = 0;

__device__ __forceinline__ float fsqrt_approx(float x) {
    float r; asm("sqrt.approx.f32 %0, %1;" : "=f"(r) : "f"(x)); return r;
}
__device__ __forceinline__ float pair_e(float dot, float sqsum) {
    float d2 = fmaf(-2.f, dot, sqsum);
    d2 = fmaxf(d2, 1e-20f);
    return __expf(-fsqrt_approx(d2));
}
__device__ __forceinline__ uint32_t bpack(__nv_bfloat16 a, __nv_bfloat16 b) {
    __nv_bfloat162 p; p.x = a; p.y = b;
    return *reinterpret_cast<uint32_t*>(&p);
}
__device__ __forceinline__ uint32_t smem_u32(const void* p) {
    uint32_t a;
    asm("{ .reg .u64 t; cvta.to.shared.u64 t, %1; cvt.u32.u64 %0, t; }" : "=r"(a) : "l"(p));
    return a;
}
__device__ __forceinline__ void mma_bf16(float* d, const uint32_t* a,
                                         const uint32_t* b, const float* c) {
    asm volatile(
        "mma.sync.aligned.m16n8k16.row.col.f32.bf16.bf16.f32 "
        "{%0,%1,%2,%3}, {%4,%5,%6,%7}, {%8,%9}, {%10,%11,%12,%13};"
        : "=f"(d[0]), "=f"(d[1]), "=f"(d[2]), "=f"(d[3])
        : "r"(a[0]), "r"(a[1]), "r"(a[2]), "r"(a[3]),
          "r"(b[0]), "r"(b[1]),
          "f"(c[0]), "f"(c[1]), "f"(c[2]), "f"(c[3]));
}
#define LDSM_X4(d, addr) \
    asm volatile("ldmatrix.sync.aligned.m8n8.x4.shared.b16 {%0,%1,%2,%3}, [%4];" \
        : "=r"((d)[0]), "=r"((d)[1]), "=r"((d)[2]), "=r"((d)[3]) : "r"(addr))

// Kernel 1: grid 72. bid<64: hi/lo split + norms. bid>=64: bucket fill + g_den zero.
__global__ void __launch_bounds__(NTHR)
prep_kernel(const float* __restrict__ z, const int* __restrict__ sid) {
    const int t = threadIdx.x;
    if (blockIdx.x < 64) {
        const int gid = blockIdx.x * NTHR + t;
        const int r = gid >> 3, c = gid & 7;
        float4 v = ((const float4*)z)[r * 8 + c];
        float s = v.x * v.x + v.y * v.y + v.z * v.z + v.w * v.w;
        s += __shfl_xor_sync(0xffffffffu, s, 1);
        s += __shfl_xor_sync(0xffffffffu, s, 2);
        s += __shfl_xor_sync(0xffffffffu, s, 4);
        if (c == 0) g_sq[r] = s;

        __nv_bfloat16 hx = __float2bfloat16(v.x), hy = __float2bfloat16(v.y);
        __nv_bfloat16 hz = __float2bfloat16(v.z), hw = __float2bfloat16(v.w);
        __nv_bfloat16 lx = __float2bfloat16(v.x - __bfloat162float(hx));
        __nv_bfloat16 ly = __float2bfloat16(v.y - __bfloat162float(hy));
        __nv_bfloat16 lz = __float2bfloat16(v.z - __bfloat162float(hz));
        __nv_bfloat16 lw = __float2bfloat16(v.w - __bfloat162float(hw));
        g_zhl[r * 32 + c * 2]          = bpack(hx, hy);
        g_zhl[r * 32 + c * 2 + 1]      = bpack(hz, hw);
        g_zhl[r * 32 + 16 + c * 2]     = bpack(lx, ly);
        g_zhl[r * 32 + 16 + c * 2 + 1] = bpack(lz, lw);
    } else {
        const int j = (blockIdx.x - 64) * NTHR + t;   // 8 CTAs cover 2048 j's
        g_den[j] = 0.f;                               // zero accumulator each replay
        const int id = sid[j];
        int slot = atomicAdd(&g_bcnt[id], 1);
        if (slot < BCAP) g_bkt[id * BCAP + slot] = j;
    }
}

// Kernel 2: grid (16, 40).
//  y<32 : den tile 128x64, mma.sync bf16 hi/lo, ldmatrix frag loads; diag skipped by index;
//         row sums atomically accumulated into g_den.
//  y>=32: sparse num/valid (warp per 2 rows).
// Last of 640 CTAs: final scalar reduction + scratch reset.
__global__ void __launch_bounds__(NTHR, 4)
main_kernel(const float* __restrict__ z,
            const int* __restrict__ knn,
            const int* __restrict__ sid,
            float* __restrict__ out) {
    __shared__ __align__(16) char s_a[MT * RS];
    __shared__ __align__(16) char s_b[NT * RS];
    __shared__ float s_pd[MT][2];
    __shared__ float s_sqi[MT];
    __shared__ float s_sqj[NT];
    __shared__ bool s_last;

    const int t = threadIdx.x;
    const int w = t >> 5, lane = t & 31;
    const int gID = lane >> 2, tig = lane & 3;
    const int x = blockIdx.x, y = blockIdx.y;

    if (y < YT) {
        // ---- load tiles: A = rows [x*128,+128), B = rows [y*64,+64) ----
        const uint4* src = (const uint4*)g_zhl;
#pragma unroll
        for (int i = t; i < (MT + NT) * 8; i += NTHR) {
            int row = i >> 3, u = i & 7;
            if (i < MT * 8)
                *(uint4*)(s_a + row * RS + u * 16) = src[(x * MT + row) * 8 + u];
            else {
                int r2 = row - MT;
                *(uint4*)(s_b + r2 * RS + u * 16) = src[(y * NT + r2) * 8 + u];
            }
        }
        if (t < MT) s_sqi[t] = g_sq[x * MT + t];
        else if (t < MT + NT) s_sqj[t - MT] = g_sq[y * NT + (t - MT)];
        __syncthreads();

        // ---- warp tile 32x32: wm in 0..3 (rows), wn in 0..1 (cols) ----
        const int wm = w & 3, wn = w >> 2;
        float acc[2][4][4];
#pragma unroll
        for (int mi = 0; mi < 2; mi++)
#pragma unroll
            for (int ni = 0; ni < 4; ni++)
#pragma unroll
                for (int q = 0; q < 4; q++) acc[mi][ni][q] = 0.f;

        // ldmatrix lane base addresses
        uint32_t aBase[2], bBase[2];
        {
            const uint32_t sa32 = smem_u32(s_a), sb32 = smem_u32(s_b);
            const int m = lane >> 3, r = lane & 7;
#pragma unroll
            for (int mi = 0; mi < 2; mi++)
                aBase[mi] = sa32 + (uint32_t)((wm * 32 + mi * 16 + (m & 1) * 8 + r) * RS
                                              + (m >> 1) * 16);
#pragma unroll
            for (int g = 0; g < 2; g++)
                bBase[g] = sb32 + (uint32_t)((wn * 32 + (g * 2 + (m >> 1)) * 8 + r) * RS
                                             + (m & 1) * 16);
        }

        // combos: 0 = hi*hi, 1 = hi*lo, 2 = lo*hi  (lo at +64B)
#pragma unroll
        for (int combo = 0; combo < 3; combo++) {
            const uint32_t aoff = (combo == 2) ? 64u : 0u;
            const uint32_t boff = (combo == 1) ? 64u : 0u;
#pragma unroll
            for (int kk = 0; kk < 2; kk++) {
                const uint32_t ko = (uint32_t)(kk * 32);
                uint32_t af[2][4], bf[2][4];
                LDSM_X4(af[0], aBase[0] + aoff + ko);
                LDSM_X4(af[1], aBase[1] + aoff + ko);
                LDSM_X4(bf[0], bBase[0] + boff + ko);   // {ni0_k0, ni0_k8, ni1_k0, ni1_k8}
                LDSM_X4(bf[1], bBase[1] + boff + ko);   // {ni2..., ni3...}
#pragma unroll
                for (int mi = 0; mi < 2; mi++) {
                    mma_bf16(acc[mi][0], af[mi], &bf[0][0], acc[mi][0]);
                    mma_bf16(acc[mi][1], af[mi], &bf[0][2], acc[mi][1]);
                    mma_bf16(acc[mi][2], af[mi], &bf[1][0], acc[mi][2]);
                    mma_bf16(acc[mi][3], af[mi], &bf[1][2], acc[mi][3]);
                }
            }
        }

        // ---- epilogue: exp(-sqrt(d2)), skip diagonal, row sums ----
#pragma unroll
        for (int mi = 0; mi < 2; mi++) {
            const int lr0 = wm * 32 + mi * 16 + gID;
            const int lr1 = lr0 + 8;
            const int gi0 = x * MT + lr0, gi1 = x * MT + lr1;
            const float sq0 = s_sqi[lr0], sq1 = s_sqi[lr1];
            float rs0 = 0.f, rs1 = 0.f;
#pragma unroll
            for (int ni = 0; ni < 4; ni++) {
                const int cl = wn * 32 + ni * 8 + tig * 2;
                const int gj0 = y * NT + cl, gj1 = gj0 + 1;
                const float sa = s_sqj[cl], sb = s_sqj[cl + 1];
                float e;
                e = pair_e(acc[mi][ni][0], sq0 + sa); rs0 += (gj0 == gi0) ? 0.f : e;
                e = pair_e(acc[mi][ni][1], sq0 + sb); rs0 += (gj1 == gi0) ? 0.f : e;
                e = pair_e(acc[mi][ni][2], sq1 + sa); rs1 += (gj0 == gi1) ? 0.f : e;
                e = pair_e(acc[mi][ni][3], sq1 + sb); rs1 += (gj1 == gi1) ? 0.f : e;
            }
            rs0 += __shfl_xor_sync(0xffffffffu, rs0, 1);
            rs0 += __shfl_xor_sync(0xffffffffu, rs0, 2);
            rs1 += __shfl_xor_sync(0xffffffffu, rs1, 1);
            rs1 += __shfl_xor_sync(0xffffffffu, rs1, 2);
            if (tig == 0) { s_pd[lr0][wn] = rs0; s_pd[lr1][wn] = rs1; }
        }
        __syncthreads();
        if (t < MT)
            atomicAdd(&g_den[x * MT + t], s_pd[t][0] + s_pd[t][1]);
    } else {
        // ---- sparse num / valid: warp handles 2 rows (128 sparse CTAs) ----
        const int ysp = y - YT;
#pragma unroll
        for (int rr = 0; rr < 2; rr++) {
            const int i = x * MT + ysp * 16 + w * 2 + rr;
            const int sidi = sid[i];
            int id = (lane < KNN) ? knn[sidi * KNN + lane] : (-1 - lane);
            unsigned mm = __match_any_sync(0xffffffffu, id);
            bool dup = (mm & ((1u << lane) - 1u)) != 0u;
            float num = 0.f;
            bool found = false;
            if (lane < KNN && !dup) {
                int cnt = g_bcnt[id];
                if (cnt > BCAP) cnt = BCAP;
                if (cnt > 0) {
                    int jarr[BCAP];
                    for (int s2 = 0; s2 < cnt; s2++) jarr[s2] = g_bkt[id * BCAP + s2];
                    for (int a = 1; a < cnt; a++) {   // sort -> deterministic order
                        int v = jarr[a]; int b = a - 1;
                        while (b >= 0 && jarr[b] > v) { jarr[b + 1] = jarr[b]; b--; }
                        jarr[b + 1] = v;
                    }
                    for (int s2 = 0; s2 < cnt; s2++) {
                        int jj = jarr[s2];
                        if (jj != i) {
                            const float* zi = z + i * DD;
                            const float* zj = z + jj * DD;
                            float dot = 0.f;
#pragma unroll
                            for (int k = 0; k < DD; k++) dot = fmaf(zi[k], zj[k], dot);
                            num += pair_e(dot, g_sq[i] + g_sq[jj]);
                            found = true;
                        }
                    }
                }
            }
#pragma unroll
            for (int off = 16; off > 0; off >>= 1)
                num += __shfl_xor_sync(0xffffffffu, num, off);
            unsigned bal = __ballot_sync(0xffffffffu, found);
            if (lane == 0) {
                g_num[i] = num;
                g_any[i] = bal ? 1.f : 0.f;
            }
        }
    }

    // ---- last-block final reduction ----
    __threadfence();
    if (t == 0) {
        unsigned old = atomicAdd(&g_cnt, 1u);
        s_last = (old == NCTAS_ALL - 1);
    }
    __syncthreads();
    if (!s_last) return;

    __threadfence();
    float tot = 0.f, cnt = 0.f;
    for (int i = t; i < BN; i += NTHR) {
        float dv = __ldcg(&g_den[i]);
        float nv = __ldcg(&g_num[i]);
        bool valid = __ldcg(&g_any[i]) > 0.f;
        float sr = nv / dv;
        float loss = -__logf(sr + 1e-8f);
        tot += valid ? loss : 0.f;
        cnt += valid ? 1.f : 0.f;
    }
#pragma unroll
    for (int off = 16; off > 0; off >>= 1) {
        tot += __shfl_xor_sync(0xffffffffu, tot, off);
        cnt += __shfl_xor_sync(0xffffffffu, cnt, off);
    }
    if (lane == 0) { s_pd[w][0] = tot; s_pd[w][1] = cnt; }
    __syncthreads();
    if (t == 0) {
        float T = 0.f, C = 0.f;
#pragma unroll
        for (int ww = 0; ww < NTHR / 32; ww++) { T += s_pd[ww][0]; C += s_pd[ww][1]; }
        out[0] = (C > 0.f) ? (T / C) : 0.f;
        g_cnt = 0;
    }
    for (int i = t; i < NIDS; i += NTHR) g_bcnt[i] = 0;  // reset for next replay
}

extern "C" void kernel_launch(void* const* d_in, const int* in_sizes, int n_in,
                              void* d_out, int out_size) {
    const float* z   = (const float*)d_in[0];
    const int*   knn = (const int*)d_in[1];
    const int*   sid = (const int*)d_in[2];
    (void)in_sizes; (void)n_in; (void)out_size;

    prep_kernel<<<72, NTHR>>>(z, sid);
    main_kernel<<<dim3(XT, YT + SPY, 1), NTHR>>>(z, knn, sid, (float*)d_out);
}

// round 16
// speedup vs baseline: 1.9786x; 1.1130x over previous
#include <cuda_runtime.h>
#include <cuda_bf16.h>
#include <cstdint>

#define BN    2048
#define DD    32
#define NIDS  8192
#define KNN   30
#define NTHR  256
#define MT    128               // rows per den tile
#define NT    64                // cols per den tile
#define NDEN  272               // # tiles with y >= 2x  (Σ_x (32-2x))
#define NSP   128               // sparse CTAs (warp per 2 rows)
#define NCTAS_ALL (NDEN + NSP)  // 400
#define BCAP  32
#define RS    144               // smem row stride: 128B (hi|lo) + 16B pad

// Scratch (no allocations allowed)
__device__ float g_sq[BN];
__device__ __align__(16) unsigned g_zhl[BN * 32];  // 128B/row: 16 u32 hi | 16 u32 lo
__device__ float g_den[BN];      // atomic fp32 accumulation (zeroed by prep)
__device__ float g_num[BN];
__device__ float g_any[BN];
__device__ int   g_bkt[NIDS * BCAP];
__device__ int   g_bcnt[NIDS];
__device__ unsigned g_cnt = 0;

__device__ __forceinline__ float fsqrt_approx(float x) {
    float r; asm("sqrt.approx.f32 %0, %1;" : "=f"(r) : "f"(x)); return r;
}
__device__ __forceinline__ float pair_e(float dot, float sqsum) {
    float d2 = fmaf(-2.f, dot, sqsum);
    d2 = fmaxf(d2, 1e-20f);
    return __expf(-fsqrt_approx(d2));
}
__device__ __forceinline__ uint32_t bpack(__nv_bfloat16 a, __nv_bfloat16 b) {
    __nv_bfloat162 p; p.x = a; p.y = b;
    return *reinterpret_cast<uint32_t*>(&p);
}
__device__ __forceinline__ uint32_t smem_u32(const void* p) {
    uint32_t a;
    asm("{ .reg .u64 t; cvta.to.shared.u64 t, %1; cvt.u32.u64 %0, t; }" : "=r"(a) : "l"(p));
    return a;
}
__device__ __forceinline__ void mma_bf16(float* d, const uint32_t* a,
                                         const uint32_t* b, const float* c) {
    asm volatile(
        "mma.sync.aligned.m16n8k16.row.col.f32.bf16.bf16.f32 "
        "{%0,%1,%2,%3}, {%4,%5,%6,%7}, {%8,%9}, {%10,%11,%12,%13};"
        : "=f"(d[0]), "=f"(d[1]), "=f"(d[2]), "=f"(d[3])
        : "r"(a[0]), "r"(a[1]), "r"(a[2]), "r"(a[3]),
          "r"(b[0]), "r"(b[1]),
          "f"(c[0]), "f"(c[1]), "f"(c[2]), "f"(c[3]));
}
#define LDSM_X4(d, addr) \
    asm volatile("ldmatrix.sync.aligned.m8n8.x4.shared.b16 {%0,%1,%2,%3}, [%4];" \
        : "=r"((d)[0]), "=r"((d)[1]), "=r"((d)[2]), "=r"((d)[3]) : "r"(addr))

// Kernel 1: grid 72. bid<64: hi/lo split + norms. bid>=64: bucket fill + g_den zero.
__global__ void __launch_bounds__(NTHR)
prep_kernel(const float* __restrict__ z, const int* __restrict__ sid) {
    const int t = threadIdx.x;
    if (blockIdx.x < 64) {
        const int gid = blockIdx.x * NTHR + t;
        const int r = gid >> 3, c = gid & 7;
        float4 v = ((const float4*)z)[r * 8 + c];
        float s = v.x * v.x + v.y * v.y + v.z * v.z + v.w * v.w;
        s += __shfl_xor_sync(0xffffffffu, s, 1);
        s += __shfl_xor_sync(0xffffffffu, s, 2);
        s += __shfl_xor_sync(0xffffffffu, s, 4);
        if (c == 0) g_sq[r] = s;

        __nv_bfloat16 hx = __float2bfloat16(v.x), hy = __float2bfloat16(v.y);
        __nv_bfloat16 hz = __float2bfloat16(v.z), hw = __float2bfloat16(v.w);
        __nv_bfloat16 lx = __float2bfloat16(v.x - __bfloat162float(hx));
        __nv_bfloat16 ly = __float2bfloat16(v.y - __bfloat162float(hy));
        __nv_bfloat16 lz = __float2bfloat16(v.z - __bfloat162float(hz));
        __nv_bfloat16 lw = __float2bfloat16(v.w - __bfloat162float(hw));
        g_zhl[r * 32 + c * 2]          = bpack(hx, hy);
        g_zhl[r * 32 + c * 2 + 1]      = bpack(hz, hw);
        g_zhl[r * 32 + 16 + c * 2]     = bpack(lx, ly);
        g_zhl[r * 32 + 16 + c * 2 + 1] = bpack(lz, lw);
    } else {
        const int j = (blockIdx.x - 64) * NTHR + t;   // 8 CTAs cover 2048 j's
        g_den[j] = 0.f;                               // zero accumulator each replay
        const int id = sid[j];
        int slot = atomicAdd(&g_bcnt[id], 1);
        if (slot < BCAP) g_bkt[id * BCAP + slot] = j;
    }
}

// Kernel 2: grid 400 (1D).
//  u<272 : symmetric den tile (x,y) with y>=2x; pairs masked to j>i, each e credited
//          to den[i] (row sum) AND den[j] (col sum).
//  u>=272: sparse num/valid (warp per 2 rows).
// Last of 400 CTAs: final scalar reduction + scratch reset.
__global__ void __launch_bounds__(NTHR, 4)
main_kernel(const float* __restrict__ z,
            const int* __restrict__ knn,
            const int* __restrict__ sid,
            float* __restrict__ out) {
    __shared__ __align__(16) char s_a[MT * RS];
    __shared__ __align__(16) char s_b[NT * RS];
    __shared__ float s_pr[MT][2];    // row partials per wn
    __shared__ float s_pc[NT][4];    // col partials per wm
    __shared__ float s_sqi[MT];
    __shared__ float s_sqj[NT];
    __shared__ bool s_last;

    const int t = threadIdx.x;
    const int w = t >> 5, lane = t & 31;
    const int gID = lane >> 2, tig = lane & 3;
    const int u = blockIdx.x;

    if (u < NDEN) {
        // decode (x, y): tiles per x = 32 - 2x, y = 2x + rem
        int x = 0, base = 0;
#pragma unroll
        for (int v = 0; v < 16; v++) {
            int cnt = 32 - 2 * v;
            if (u >= base && u < base + cnt) x = v;
            base += (u >= base + cnt) ? 0 : 0;   // keep base semantics below
        }
        // recompute base for chosen x (cum(x) = 33x - x^2)
        int cum = 33 * x - x * x;
        // fix x if decode loop above picked wrong (robust linear scan)
        while (u < cum) { x--; cum = 33 * x - x * x; }
        while (u >= cum + (32 - 2 * x)) { x++; cum = 33 * x - x * x; }
        const int y = 2 * x + (u - cum);

        // ---- load tiles: A = rows [x*128,+128), B = rows [y*64,+64) ----
        const uint4* src = (const uint4*)g_zhl;
#pragma unroll
        for (int i = t; i < (MT + NT) * 8; i += NTHR) {
            int row = i >> 3, uu = i & 7;
            if (i < MT * 8)
                *(uint4*)(s_a + row * RS + uu * 16) = src[(x * MT + row) * 8 + uu];
            else {
                int r2 = row - MT;
                *(uint4*)(s_b + r2 * RS + uu * 16) = src[(y * NT + r2) * 8 + uu];
            }
        }
        if (t < MT) s_sqi[t] = g_sq[x * MT + t];
        else if (t < MT + NT) s_sqj[t - MT] = g_sq[y * NT + (t - MT)];
        if (t < NT) { s_pc[t][0] = 0.f; s_pc[t][1] = 0.f; s_pc[t][2] = 0.f; s_pc[t][3] = 0.f; }
        __syncthreads();

        // ---- warp tile 32x32: wm in 0..3 (rows), wn in 0..1 (cols) ----
        const int wm = w & 3, wn = w >> 2;
        float acc[2][4][4];
#pragma unroll
        for (int mi = 0; mi < 2; mi++)
#pragma unroll
            for (int ni = 0; ni < 4; ni++)
#pragma unroll
                for (int q = 0; q < 4; q++) acc[mi][ni][q] = 0.f;

        uint32_t aBase[2], bBase[2];
        {
            const uint32_t sa32 = smem_u32(s_a), sb32 = smem_u32(s_b);
            const int m = lane >> 3, r = lane & 7;
#pragma unroll
            for (int mi = 0; mi < 2; mi++)
                aBase[mi] = sa32 + (uint32_t)((wm * 32 + mi * 16 + (m & 1) * 8 + r) * RS
                                              + (m >> 1) * 16);
#pragma unroll
            for (int g = 0; g < 2; g++)
                bBase[g] = sb32 + (uint32_t)((wn * 32 + (g * 2 + (m >> 1)) * 8 + r) * RS
                                             + (m & 1) * 16);
        }

        // combos: 0 = hi*hi, 1 = hi*lo, 2 = lo*hi  (lo at +64B)
#pragma unroll
        for (int combo = 0; combo < 3; combo++) {
            const uint32_t aoff = (combo == 2) ? 64u : 0u;
            const uint32_t boff = (combo == 1) ? 64u : 0u;
#pragma unroll
            for (int kk = 0; kk < 2; kk++) {
                const uint32_t ko = (uint32_t)(kk * 32);
                uint32_t af[2][4], bf[2][4];
                LDSM_X4(af[0], aBase[0] + aoff + ko);
                LDSM_X4(af[1], aBase[1] + aoff + ko);
                LDSM_X4(bf[0], bBase[0] + boff + ko);
                LDSM_X4(bf[1], bBase[1] + boff + ko);
#pragma unroll
                for (int mi = 0; mi < 2; mi++) {
                    mma_bf16(acc[mi][0], af[mi], &bf[0][0], acc[mi][0]);
                    mma_bf16(acc[mi][1], af[mi], &bf[0][2], acc[mi][1]);
                    mma_bf16(acc[mi][2], af[mi], &bf[1][0], acc[mi][2]);
                    mma_bf16(acc[mi][3], af[mi], &bf[1][2], acc[mi][3]);
                }
            }
        }

        // ---- epilogue: mask j>i, row sums AND col sums ----
        float cs0[4] = {0.f, 0.f, 0.f, 0.f};
        float cs1[4] = {0.f, 0.f, 0.f, 0.f};
#pragma unroll
        for (int mi = 0; mi < 2; mi++) {
            const int lr0 = wm * 32 + mi * 16 + gID;
            const int lr1 = lr0 + 8;
            const int gi0 = x * MT + lr0, gi1 = x * MT + lr1;
            const float sq0 = s_sqi[lr0], sq1 = s_sqi[lr1];
            float rs0 = 0.f, rs1 = 0.f;
#pragma unroll
            for (int ni = 0; ni < 4; ni++) {
                const int cl = wn * 32 + ni * 8 + tig * 2;
                const int gj0 = y * NT + cl, gj1 = gj0 + 1;
                const float sa = s_sqj[cl], sb = s_sqj[cl + 1];
                float e00 = pair_e(acc[mi][ni][0], sq0 + sa); e00 = (gj0 > gi0) ? e00 : 0.f;
                float e01 = pair_e(acc[mi][ni][1], sq0 + sb); e01 = (gj1 > gi0) ? e01 : 0.f;
                float e10 = pair_e(acc[mi][ni][2], sq1 + sa); e10 = (gj0 > gi1) ? e10 : 0.f;
                float e11 = pair_e(acc[mi][ni][3], sq1 + sb); e11 = (gj1 > gi1) ? e11 : 0.f;
                rs0 += e00 + e01;
                rs1 += e10 + e11;
                cs0[ni] += e00 + e10;
                cs1[ni] += e01 + e11;
            }
            rs0 += __shfl_xor_sync(0xffffffffu, rs0, 1);
            rs0 += __shfl_xor_sync(0xffffffffu, rs0, 2);
            rs1 += __shfl_xor_sync(0xffffffffu, rs1, 1);
            rs1 += __shfl_xor_sync(0xffffffffu, rs1, 2);
            if (tig == 0) { s_pr[lr0][wn] = rs0; s_pr[lr1][wn] = rs1; }
        }
        // column reduce over gID (lanes differing in bits 2..4)
#pragma unroll
        for (int ni = 0; ni < 4; ni++) {
#pragma unroll
            for (int off = 4; off <= 16; off <<= 1) {
                cs0[ni] += __shfl_xor_sync(0xffffffffu, cs0[ni], off);
                cs1[ni] += __shfl_xor_sync(0xffffffffu, cs1[ni], off);
            }
        }
        if (gID == 0) {
#pragma unroll
            for (int ni = 0; ni < 4; ni++) {
                const int cl = wn * 32 + ni * 8 + tig * 2;
                s_pc[cl][wm]     = (wm == (w & 3)) ? s_pc[cl][wm] : s_pc[cl][wm];
                s_pc[cl][wm]     += 0.f;   // no-op keep layout
                atomicAdd(&s_pc[cl][wm], cs0[ni]);
                atomicAdd(&s_pc[cl + 1][wm], cs1[ni]);
            }
        }
        __syncthreads();
        if (t < MT)
            atomicAdd(&g_den[x * MT + t], s_pr[t][0] + s_pr[t][1]);
        else if (t < MT + NT) {
            int c = t - MT;
            atomicAdd(&g_den[y * NT + c],
                      (s_pc[c][0] + s_pc[c][1]) + (s_pc[c][2] + s_pc[c][3]));
        }
    } else {
        // ---- sparse num / valid: warp handles 2 rows (128 sparse CTAs) ----
        const int s = u - NDEN;            // 0..127
#pragma unroll
        for (int rr = 0; rr < 2; rr++) {
            const int i = s * 16 + w * 2 + rr;
            const int sidi = sid[i];
            int id = (lane < KNN) ? knn[sidi * KNN + lane] : (-1 - lane);
            unsigned mm = __match_any_sync(0xffffffffu, id);
            bool dup = (mm & ((1u << lane) - 1u)) != 0u;
            float num = 0.f;
            bool found = false;
            if (lane < KNN && !dup) {
                int cnt = g_bcnt[id];
                if (cnt > BCAP) cnt = BCAP;
                if (cnt > 0) {
                    int jarr[BCAP];
                    for (int s2 = 0; s2 < cnt; s2++) jarr[s2] = g_bkt[id * BCAP + s2];
                    for (int a = 1; a < cnt; a++) {
                        int v = jarr[a]; int b = a - 1;
                        while (b >= 0 && jarr[b] > v) { jarr[b + 1] = jarr[b]; b--; }
                        jarr[b + 1] = v;
                    }
                    for (int s2 = 0; s2 < cnt; s2++) {
                        int jj = jarr[s2];
                        if (jj != i) {
                            const float* zi = z + i * DD;
                            const float* zj = z + jj * DD;
                            float dot = 0.f;
#pragma unroll
                            for (int k = 0; k < DD; k++) dot = fmaf(zi[k], zj[k], dot);
                            num += pair_e(dot, g_sq[i] + g_sq[jj]);
                            found = true;
                        }
                    }
                }
            }
#pragma unroll
            for (int off = 16; off > 0; off >>= 1)
                num += __shfl_xor_sync(0xffffffffu, num, off);
            unsigned bal = __ballot_sync(0xffffffffu, found);
            if (lane == 0) {
                g_num[i] = num;
                g_any[i] = bal ? 1.f : 0.f;
            }
        }
    }

    // ---- last-block final reduction ----
    __threadfence();
    if (t == 0) {
        unsigned old = atomicAdd(&g_cnt, 1u);
        s_last = (old == NCTAS_ALL - 1);
    }
    __syncthreads();
    if (!s_last) return;

    __threadfence();
    float tot = 0.f, cnt = 0.f;
    for (int i = t; i < BN; i += NTHR) {
        float dv = __ldcg(&g_den[i]);
        float nv = __ldcg(&g_num[i]);
        bool valid = __ldcg(&g_any[i]) > 0.f;
        float sr = nv / dv;
        float loss = -__logf(sr + 1e-8f);
        tot += valid ? loss : 0.f;
        cnt += valid ? 1.f : 0.f;
    }
#pragma unroll
    for (int off = 16; off > 0; off >>= 1) {
        tot += __shfl_xor_sync(0xffffffffu, tot, off);
        cnt += __shfl_xor_sync(0xffffffffu, cnt, off);
    }
    if (lane == 0) { s_pr[w][0] = tot; s_pr[w][1] = cnt; }
    __syncthreads();
    if (t == 0) {
        float T = 0.f, C = 0.f;
#pragma unroll
        for (int ww = 0; ww < NTHR / 32; ww++) { T += s_pr[ww][0]; C += s_pr[ww][1]; }
        out[0] = (C > 0.f) ? (T / C) : 0.f;
        g_cnt = 0;
    }
    for (int i = t; i < NIDS; i += NTHR) g_bcnt[i] = 0;  // reset for next replay
}

extern "C" void kernel_launch(void* const* d_in, const int* in_sizes, int n_in,
                              void* d_out, int out_size) {
    const float* z   = (const float*)d_in[0];
    const int*   knn = (const int*)d_in[1];
    const int*   sid = (const int*)d_in[2];
    (void)in_sizes; (void)n_in; (void)out_size;

    prep_kernel<<<72, NTHR>>>(z, sid);
    main_kernel<<<NCTAS_ALL, NTHR>>>(z, knn, sid, (float*)d_out);
}